// round 14
// baseline (speedup 1.0000x reference)
#include <cuda_runtime.h>
#include <cuda_fp16.h>
#include <cstdint>

#define Bt  2
#define Ss  2048
#define Dd  1024
#define Hh  16
#define HDd 64
#define Tt  (Bt * Ss)      // 4096 tokens
#define DFF (4 * Dd)       // 4096
#define QKVS (3 * Dd)      // 3072

// ---------------- scratch (device globals; no allocation allowed) ----------------
__device__ float  g_proj[Tt * Dd];
__device__ float  g_x1[Tt * Dd];
__device__ float  g_bqkv[QKVS];
__device__ __half g_xh[Tt * Dd];
__device__ __half g_wqkvh[(size_t)Dd * QKVS];
__device__ __half g_woh[Dd * Dd];
__device__ __half g_wuph[(size_t)Dd * DFF];
__device__ __half g_wdnh[(size_t)DFF * Dd];
__device__ __half g_qkvh[(size_t)Tt * QKVS];
__device__ __half g_midh[Tt * Dd];
__device__ __half g_x1h[Tt * Dd];
__device__ __half g_uph[(size_t)Tt * DFF];

// ---------------- helpers ----------------
__device__ __forceinline__ void mma_f16(float* d, const uint32_t* a, const uint32_t* b) {
    asm volatile(
        "mma.sync.aligned.m16n8k16.row.col.f32.f16.f16.f32 "
        "{%0,%1,%2,%3}, {%4,%5,%6,%7}, {%8,%9}, {%0,%1,%2,%3};"
        : "+f"(d[0]), "+f"(d[1]), "+f"(d[2]), "+f"(d[3])
        : "r"(a[0]), "r"(a[1]), "r"(a[2]), "r"(a[3]), "r"(b[0]), "r"(b[1]));
}
__device__ __forceinline__ uint32_t sptr(const void* p) {
    return (uint32_t)__cvta_generic_to_shared(p);
}
__device__ __forceinline__ void ldsm_x4(uint32_t* r, uint32_t addr) {
    asm volatile("ldmatrix.sync.aligned.m8n8.x4.shared.b16 {%0,%1,%2,%3}, [%4];"
                 : "=r"(r[0]), "=r"(r[1]), "=r"(r[2]), "=r"(r[3]) : "r"(addr));
}
__device__ __forceinline__ void ldsm_x4t(uint32_t* r, uint32_t addr) {
    asm volatile("ldmatrix.sync.aligned.m8n8.x4.trans.shared.b16 {%0,%1,%2,%3}, [%4];"
                 : "=r"(r[0]), "=r"(r[1]), "=r"(r[2]), "=r"(r[3]) : "r"(addr));
}
__device__ __forceinline__ void ldsm_x2t(uint32_t* r, uint32_t addr) {
    asm volatile("ldmatrix.sync.aligned.m8n8.x2.trans.shared.b16 {%0,%1}, [%2];"
                 : "=r"(r[0]), "=r"(r[1]) : "r"(addr));
}
__device__ __forceinline__ uint32_t packh2(float x, float y) {
    __half2 h = __floats2half2_rn(x, y);
    return *reinterpret_cast<uint32_t*>(&h);
}
__device__ __forceinline__ void cp_async16(uint32_t dst, const void* src) {
    asm volatile("cp.async.cg.shared.global [%0], [%1], 16;" :: "r"(dst), "l"(src));
}
__device__ __forceinline__ void cp_commit() {
    asm volatile("cp.async.commit_group;" ::: "memory");
}
template <int N>
__device__ __forceinline__ void cp_wait() {
    asm volatile("cp.async.wait_group %0;" :: "n"(N) : "memory");
}

// ---------------- fp32 -> fp16 converters (consolidated) ----------------
#define DD4 (Dd * Dd / 4)
__global__ __launch_bounds__(256)
void f2h_qkv(const float* __restrict__ Wq, const float* __restrict__ Wk,
             const float* __restrict__ Wv, __half* __restrict__ out)
{
    const int idx = blockIdx.x * 256 + threadIdx.x;
    const int seg = idx / DD4;
    const int j = (idx - seg * DD4) * 4;
    const float* W = (seg == 0) ? Wq : (seg == 1) ? Wk : Wv;
    const int r = j >> 10, c = j & 1023;
    float4 v = *(const float4*)&W[j];
    __half* o = out + (size_t)r * QKVS + seg * Dd + c;
    *(__half2*)&o[0] = __floats2half2_rn(v.x, v.y);
    *(__half2*)&o[2] = __floats2half2_rn(v.z, v.w);
}
__global__ __launch_bounds__(256)
void f2h_misc(const float* __restrict__ x,   const float* __restrict__ Wo,
              const float* __restrict__ Wup, const float* __restrict__ Wdn,
              __half* __restrict__ xh,   __half* __restrict__ woh,
              __half* __restrict__ wuph, __half* __restrict__ wdnh)
{
    const int c0 = Tt * Dd / 4, c1 = Dd * Dd / 4, c2 = Dd * DFF / 4;
    int idx = blockIdx.x * 256 + threadIdx.x;
    const float* in; __half* out;
    if (idx < c0)                 { in = x;   out = xh; }
    else if ((idx -= c0) < c1)    { in = Wo;  out = woh; }
    else if ((idx -= c1) < c2)    { in = Wup; out = wuph; }
    else { idx -= c2;               in = Wdn; out = wdnh; }
    const int j = idx * 4;
    float4 v = *(const float4*)&in[j];
    *(__half2*)&out[j]     = __floats2half2_rn(v.x, v.y);
    *(__half2*)&out[j + 2] = __floats2half2_rn(v.z, v.w);
}
__global__ __launch_bounds__(256)
void bias_concat_kernel(const float* __restrict__ bq, const float* __restrict__ bk,
                        const float* __restrict__ bv, float* __restrict__ out)
{
    const int i = blockIdx.x * 256 + threadIdx.x;
    if (i < Dd)            out[i] = bq[i];
    else if (i < 2 * Dd)   out[i] = bk[i - Dd];
    else if (i < 3 * Dd)   out[i] = bv[i - 2 * Dd];
}

// ---------------- FP16 GEMM: 128x128 tile, 512 thr (16 warps, 32x32 warp tile) ----------------
// K-chunk 64, 3-stage cp.async, 96KB dynamic smem, 2 CTAs/SM.
// A stage: 128 rows x 128B, phys16 = c ^ (r&7). B stage: 64 rows x 256B, same swizzle.
template <int RELU, int OUTH>
__global__ __launch_bounds__(512, 2)
void gemm_h(const __half* __restrict__ A, const __half* __restrict__ W,
            const float* __restrict__ bias, void* __restrict__ Cout,
            int M, int N, int K)
{
    extern __shared__ __align__(128) __half sm[];

    const int tid  = threadIdx.x;
    const int lane = tid & 31;
    const int wid  = tid >> 5;           // 0..15
    const int wm   = (wid & 3) * 32;     // 4 m-groups
    const int wn   = (wid >> 2) * 32;    // 4 n-groups
    const int m0   = blockIdx.y << 7;
    const int n0   = blockIdx.x << 7;

    const int row  = lane >> 2;
    const int col  = lane & 3;
    const int lrow = lane & 15;
    const int lc0  = lane >> 4;          // 0/1
    const uint32_t sw = (uint32_t)(lane & 7);   // swizzle XOR term for all ldsm

    const uint32_t SA0 = sptr(sm);          // A stages: [0, 49152)
    const uint32_t SB0 = SA0 + 49152;       // B stages: [49152, 98304)

    // cp.async: A rows tid>>3 (0..63, +64), chunk tid&7; B rows tid>>4 (0..31, +32), chunk tid&15
    const int a_r  = tid >> 3;
    const int a_cc = tid & 7;
    const int b_r  = tid >> 4;
    const int b_cc = tid & 15;
    const uint32_t dA = a_r * 128 + ((uint32_t)(a_cc ^ (a_r & 7)) << 4);
    const uint32_t dB = b_r * 256 + ((uint32_t)(b_cc ^ (b_r & 7)) << 4);

    float acc[2][4][4];
#pragma unroll
    for (int mi = 0; mi < 2; mi++)
#pragma unroll
        for (int ni = 0; ni < 4; ni++)
#pragma unroll
            for (int j = 0; j < 4; j++) acc[mi][ni][j] = 0.f;

    const int nk = K >> 6;

    auto load_stage = [&](int c, int st) {
        const __half* Ab = A + (size_t)(m0 + a_r) * K + (c << 6) + a_cc * 8;
        const uint32_t da = SA0 + st * 16384 + dA;
        cp_async16(da,        Ab);
        cp_async16(da + 8192, Ab + (size_t)64 * K);
        const __half* Bb = W + (size_t)((c << 6) + b_r) * N + n0 + b_cc * 8;
        const uint32_t db = SB0 + st * 16384 + dB;
        cp_async16(db,        Bb);
        cp_async16(db + 8192, Bb + (size_t)32 * N);
    };

    load_stage(0, 0); cp_commit();
    if (nk > 1) { load_stage(1, 1); cp_commit(); }

    int st = 0, stL = 2;
    for (int c = 0; c < nk; c++) {
        if (c + 1 < nk) cp_wait<1>(); else cp_wait<0>();
        __syncthreads();
        if (c + 2 < nk) { load_stage(c + 2, stL); cp_commit(); }

        const uint32_t SA = SA0 + st * 16384;
        const uint32_t SB = SB0 + st * 16384;
        const uint32_t abase = SA + (uint32_t)(wm + lrow) * 128;   // (wm+lrow)&7 == sw
        const uint32_t bq0 = ((uint32_t)((wn >> 3) + lc0) ^ sw) << 4;
        const uint32_t bq1 = ((uint32_t)((wn >> 3) + 2 + lc0) ^ sw) << 4;

#pragma unroll
        for (int ks = 0; ks < 4; ks++) {
            uint32_t a[2][4], t0[4], t1[4];
            const uint32_t ach = ((uint32_t)(2 * ks + lc0) ^ sw) << 4;
            ldsm_x4(a[0], abase + ach);
            ldsm_x4(a[1], abase + 2048 + ach);       // +16 rows
            const uint32_t bbase = SB + (uint32_t)(ks * 16 + lrow) * 256;
            ldsm_x4t(t0, bbase + bq0);               // b-frags ni=0,1
            ldsm_x4t(t1, bbase + bq1);               // b-frags ni=2,3
#pragma unroll
            for (int mi = 0; mi < 2; mi++) {
                mma_f16(acc[mi][0], a[mi], &t0[0]);
                mma_f16(acc[mi][1], a[mi], &t0[2]);
                mma_f16(acc[mi][2], a[mi], &t1[0]);
                mma_f16(acc[mi][3], a[mi], &t1[2]);
            }
        }

        st  = (st  == 2) ? 0 : st + 1;
        stL = (stL == 2) ? 0 : stL + 1;
    }

    // epilogue: direct stores
#pragma unroll
    for (int mi = 0; mi < 2; mi++) {
        const int r0 = m0 + wm + mi * 16 + row;
#pragma unroll
        for (int ni = 0; ni < 4; ni++) {
            const int c0 = n0 + wn + ni * 8 + 2 * col;
            const float bb0 = bias[c0], bb1 = bias[c0 + 1];
            float v00 = acc[mi][ni][0] + bb0, v01 = acc[mi][ni][1] + bb1;
            float v10 = acc[mi][ni][2] + bb0, v11 = acc[mi][ni][3] + bb1;
            if (RELU) {
                v00 = fmaxf(v00, 0.f); v01 = fmaxf(v01, 0.f);
                v10 = fmaxf(v10, 0.f); v11 = fmaxf(v11, 0.f);
            }
            if (OUTH) {
                __half* Ch = (__half*)Cout;
                *(__half2*)&Ch[(size_t)r0 * N + c0]       = __floats2half2_rn(v00, v01);
                *(__half2*)&Ch[(size_t)(r0 + 8) * N + c0] = __floats2half2_rn(v10, v11);
            } else {
                float* Cf = (float*)Cout;
                *(float2*)&Cf[(size_t)r0 * N + c0]       = make_float2(v00, v01);
                *(float2*)&Cf[(size_t)(r0 + 8) * N + c0] = make_float2(v10, v11);
            }
        }
    }
}

// ---------------- FP16 causal flash attention (unchanged) ----------------
__global__ __launch_bounds__(256)
void attn_f16(const __half* __restrict__ QKV, __half* __restrict__ Og)
{
    __shared__ __half Ks[2][64][72];
    __shared__ __half Vs[2][64][72];

    const int tid  = threadIdx.x;
    const int lane = tid & 31;
    const int wid  = tid >> 5;
    const int g    = lane >> 2;
    const int t    = lane & 3;
    const int lrow = lane & 15;
    const int qb   = (int)gridDim.x - 1 - (int)blockIdx.x;
    const int bh   = blockIdx.y;
    const int b    = bh >> 4, h = bh & 15;

    const __half* Qb = QKV + (size_t)b * Ss * QKVS + h * HDd;
    const __half* Kb = Qb + Dd;
    const __half* Vb = Qb + 2 * Dd;

    const __half2 hs = __floats2half2_rn(0.125f, 0.125f);
    for (int i = tid; i < 128 * 8; i += 256) {
        const int r = i >> 3, c8 = (i & 7) * 8;
        uint4 q4 = *(const uint4*)&Qb[(size_t)(qb * 128 + r) * QKVS + c8];
        __half2* p = (__half2*)&q4;
        p[0] = __hmul2(p[0], hs); p[1] = __hmul2(p[1], hs);
        p[2] = __hmul2(p[2], hs); p[3] = __hmul2(p[3], hs);
        if (r < 64) *(uint4*)&Ks[0][r][c8]      = q4;
        else        *(uint4*)&Vs[0][r - 64][c8] = q4;
    }
    __syncthreads();

    uint32_t qf[4][4];
    {
        const __half (*Qs)[72] = (wid < 4) ? Ks[0] : Vs[0];
        const int qr = (wid * 16) % 64 + g;
#pragma unroll
        for (int s = 0; s < 4; s++) {
            qf[s][0] = *(const uint32_t*)&Qs[qr][s * 16 + 2 * t];
            qf[s][1] = *(const uint32_t*)&Qs[qr + 8][s * 16 + 2 * t];
            qf[s][2] = *(const uint32_t*)&Qs[qr][s * 16 + 2 * t + 8];
            qf[s][3] = *(const uint32_t*)&Qs[qr + 8][s * 16 + 2 * t + 8];
        }
    }
    __syncthreads();

    const int kv_r = tid >> 3;
    const int kv_c = (tid & 7) * 8;

    auto load_kv = [&](int kt, int st) {
#pragma unroll
        for (int j = 0; j < 2; j++) {
            const int r = kv_r + j * 32;
            const size_t off = (size_t)(kt * 64 + r) * QKVS + kv_c;
            cp_async16(sptr(&Ks[st][r][kv_c]), Kb + off);
            cp_async16(sptr(&Vs[st][r][kv_c]), Vb + off);
        }
    };

    load_kv(0, 0);
    cp_commit();

    float m0 = -1e30f, m1 = -1e30f, l0 = 0.f, l1 = 0.f;
    float O[8][4];
#pragma unroll
    for (int n = 0; n < 8; n++)
#pragma unroll
        for (int j = 0; j < 4; j++) O[n][j] = 0.f;

    const int lq0 = wid * 16 + g;
    const int qg0 = qb * 128 + lq0;
    const int qg1 = qg0 + 8;
    const int wmax = qb * 128 + wid * 16 + 15;

    const int nkt = 2 * qb + 2;
    for (int kt = 0; kt < nkt; kt++) {
        const int st = kt & 1;
        __syncthreads();
        if (kt + 1 < nkt) {
            load_kv(kt + 1, st ^ 1);
            cp_commit();
            cp_wait<1>();
        } else {
            cp_wait<0>();
        }
        __syncthreads();

        if (kt * 64 > wmax) continue;

        float S[8][4];
#pragma unroll
        for (int n = 0; n < 8; n++)
#pragma unroll
            for (int j = 0; j < 4; j++) S[n][j] = 0.f;

#pragma unroll
        for (int s = 0; s < 4; s++) {
#pragma unroll
            for (int n = 0; n < 8; n++) {
                uint32_t bq[2];
                bq[0] = *(const uint32_t*)&Ks[st][n * 8 + g][s * 16 + 2 * t];
                bq[1] = *(const uint32_t*)&Ks[st][n * 8 + g][s * 16 + 2 * t + 8];
                mma_f16(S[n], qf[s], bq);
            }
        }

        if (kt >= 2 * qb) {
#pragma unroll
            for (int n = 0; n < 8; n++) {
                const int kg = kt * 64 + n * 8 + 2 * t;
                if (kg     > qg0) S[n][0] = -1e30f;
                if (kg + 1 > qg0) S[n][1] = -1e30f;
                if (kg     > qg1) S[n][2] = -1e30f;
                if (kg + 1 > qg1) S[n][3] = -1e30f;
            }
        }

        float mx0 = -1e30f, mx1 = -1e30f;
#pragma unroll
        for (int n = 0; n < 8; n++) {
            mx0 = fmaxf(mx0, fmaxf(S[n][0], S[n][1]));
            mx1 = fmaxf(mx1, fmaxf(S[n][2], S[n][3]));
        }
        mx0 = fmaxf(mx0, __shfl_xor_sync(0xffffffffu, mx0, 1));
        mx0 = fmaxf(mx0, __shfl_xor_sync(0xffffffffu, mx0, 2));
        mx1 = fmaxf(mx1, __shfl_xor_sync(0xffffffffu, mx1, 1));
        mx1 = fmaxf(mx1, __shfl_xor_sync(0xffffffffu, mx1, 2));

        const float mn0 = fmaxf(m0, mx0), mn1 = fmaxf(m1, mx1);
        const float fac0 = __expf(m0 - mn0), fac1 = __expf(m1 - mn1);

        float s0 = 0.f, s1 = 0.f;
#pragma unroll
        for (int n = 0; n < 8; n++) {
            S[n][0] = __expf(S[n][0] - mn0);
            S[n][1] = __expf(S[n][1] - mn0);
            S[n][2] = __expf(S[n][2] - mn1);
            S[n][3] = __expf(S[n][3] - mn1);
            s0 += S[n][0] + S[n][1];
            s1 += S[n][2] + S[n][3];
        }
        s0 += __shfl_xor_sync(0xffffffffu, s0, 1);
        s0 += __shfl_xor_sync(0xffffffffu, s0, 2);
        s1 += __shfl_xor_sync(0xffffffffu, s1, 1);
        s1 += __shfl_xor_sync(0xffffffffu, s1, 2);

        l0 = l0 * fac0 + s0;
        l1 = l1 * fac1 + s1;
        m0 = mn0; m1 = mn1;

#pragma unroll
        for (int n = 0; n < 8; n++) {
            O[n][0] *= fac0; O[n][1] *= fac0;
            O[n][2] *= fac1; O[n][3] *= fac1;
        }

#pragma unroll
        for (int kk = 0; kk < 4; kk++) {
            uint32_t pa[4];
            pa[0] = packh2(S[2 * kk][0],     S[2 * kk][1]);
            pa[1] = packh2(S[2 * kk][2],     S[2 * kk][3]);
            pa[2] = packh2(S[2 * kk + 1][0], S[2 * kk + 1][1]);
            pa[3] = packh2(S[2 * kk + 1][2], S[2 * kk + 1][3]);
#pragma unroll
            for (int nd = 0; nd < 8; nd++) {
                uint32_t bv[2];
                ldsm_x2t(bv, sptr(&Vs[st][kk * 16 + lrow][nd * 8]));
                mma_f16(O[nd], pa, bv);
            }
        }
    }

    const float inv0 = 1.f / l0, inv1 = 1.f / l1;
    __half* o0 = Og + (size_t)(b * Ss + qb * 128 + lq0) * Dd + h * HDd;
    __half* o1 = o0 + 8 * Dd;
#pragma unroll
    for (int nd = 0; nd < 8; nd++) {
        const int c0 = nd * 8 + 2 * t;
        *(__half2*)&o0[c0] = __floats2half2_rn(O[nd][0] * inv0, O[nd][1] * inv0);
        *(__half2*)&o1[c0] = __floats2half2_rn(O[nd][2] * inv1, O[nd][3] * inv1);
    }
}

// ---------------- residual add + LayerNorm (optional fp16 mirror) ----------------
template <int DUAL>
__global__ __launch_bounds__(256)
void add_ln_kernel(const float* __restrict__ a, const float* __restrict__ r,
                   const float* __restrict__ gamma, const float* __restrict__ beta,
                   float* __restrict__ out, __half* __restrict__ outh)
{
    const int t = blockIdx.x;
    const int tid = threadIdx.x;
    __shared__ float buf[Dd];
    __shared__ float red[20];

    float s = 0.f, sq = 0.f;
    for (int i = tid; i < Dd; i += 256) {
        float v = a[(size_t)t * Dd + i] + r[(size_t)t * Dd + i];
        buf[i] = v;
        s += v; sq += v * v;
    }
#pragma unroll
    for (int o = 16; o; o >>= 1) {
        s  += __shfl_xor_sync(0xffffffffu, s, o);
        sq += __shfl_xor_sync(0xffffffffu, sq, o);
    }
    if ((tid & 31) == 0) { red[tid >> 5] = s; red[8 + (tid >> 5)] = sq; }
    __syncthreads();
    if (tid == 0) {
        float ts = 0.f, tq = 0.f;
        for (int i = 0; i < 8; i++) { ts += red[i]; tq += red[8 + i]; }
        const float mu  = ts * (1.0f / Dd);
        const float var = tq * (1.0f / Dd) - mu * mu;
        red[16] = mu;
        red[17] = rsqrtf(var + 1e-6f);
    }
    __syncthreads();
    const float mu = red[16], rstd = red[17];
    for (int i = tid; i < Dd; i += 256) {
        const float v = (buf[i] - mu) * rstd * gamma[i] + beta[i];
        out[(size_t)t * Dd + i] = v;
        if (DUAL) outh[(size_t)t * Dd + i] = __float2half_rn(v);
    }
}

// ---------------- launch ----------------
extern "C" void kernel_launch(void* const* d_in, const int* in_sizes, int n_in,
                              void* d_out, int out_size)
{
    const float* x   = (const float*)d_in[0];
    const float* Wq  = (const float*)d_in[1];
    const float* bq  = (const float*)d_in[2];
    const float* Wk  = (const float*)d_in[3];
    const float* bk  = (const float*)d_in[4];
    const float* Wv  = (const float*)d_in[5];
    const float* bv  = (const float*)d_in[6];
    const float* Wo  = (const float*)d_in[7];
    const float* bo  = (const float*)d_in[8];
    const float* g1  = (const float*)d_in[9];
    const float* b1  = (const float*)d_in[10];
    const float* Wup = (const float*)d_in[11];
    const float* bup = (const float*)d_in[12];
    const float* Wdn = (const float*)d_in[13];
    const float* bdn = (const float*)d_in[14];
    const float* g2  = (const float*)d_in[15];
    const float* b2  = (const float*)d_in[16];
    float* out = (float*)d_out;

    float *proj, *x1, *bqkv;
    __half *xh, *wqkvh, *woh, *wuph, *wdnh;
    __half *qkvh, *midh, *x1h, *uph;
    cudaGetSymbolAddress((void**)&proj,  g_proj);
    cudaGetSymbolAddress((void**)&x1,    g_x1);
    cudaGetSymbolAddress((void**)&bqkv,  g_bqkv);
    cudaGetSymbolAddress((void**)&xh,    g_xh);
    cudaGetSymbolAddress((void**)&wqkvh, g_wqkvh);
    cudaGetSymbolAddress((void**)&woh,   g_woh);
    cudaGetSymbolAddress((void**)&wuph,  g_wuph);
    cudaGetSymbolAddress((void**)&wdnh,  g_wdnh);
    cudaGetSymbolAddress((void**)&qkvh,  g_qkvh);
    cudaGetSymbolAddress((void**)&midh,  g_midh);
    cudaGetSymbolAddress((void**)&x1h,   g_x1h);
    cudaGetSymbolAddress((void**)&uph,   g_uph);

    const dim3 blk(256);
    const dim3 blkG(512);
    const int SMEM = 98304;   // 96KB dynamic, 3 stages

    cudaFuncSetAttribute(gemm_h<0, 1>, cudaFuncAttributeMaxDynamicSharedMemorySize, SMEM);
    cudaFuncSetAttribute(gemm_h<0, 0>, cudaFuncAttributeMaxDynamicSharedMemorySize, SMEM);
    cudaFuncSetAttribute(gemm_h<1, 1>, cudaFuncAttributeMaxDynamicSharedMemorySize, SMEM);

    f2h_qkv<<<3 * (Dd * Dd / 4) / 256, blk>>>(Wq, Wk, Wv, wqkvh);
    {
        const int chunks = (Tt * Dd + Dd * Dd + Dd * DFF + DFF * Dd) / 4;
        f2h_misc<<<chunks / 256, blk>>>(x, Wo, Wup, Wdn, xh, woh, wuph, wdnh);
    }
    bias_concat_kernel<<<QKVS / 256, blk>>>(bq, bk, bv, bqkv);

    gemm_h<0, 1><<<dim3(QKVS / 128, Tt / 128), blkG, SMEM>>>(xh, wqkvh, bqkv, qkvh, Tt, QKVS, Dd);

    attn_f16<<<dim3(Ss / 128, Bt * Hh), blk>>>(qkvh, midh);

    gemm_h<0, 0><<<dim3(Dd / 128, Tt / 128), blkG, SMEM>>>(midh, woh, bo, proj, Tt, Dd, Dd);
    add_ln_kernel<1><<<Tt, blk>>>(x, proj, g1, b1, x1, x1h);

    gemm_h<1, 1><<<dim3(DFF / 128, Tt / 128), blkG, SMEM>>>(x1h, wuph, bup, uph, Tt, DFF, Dd);
    gemm_h<0, 0><<<dim3(Dd / 128, Tt / 128), blkG, SMEM>>>(uph, wdnh, bdn, proj, Tt, Dd, DFF);
    add_ln_kernel<0><<<Tt, blk>>>(x1, proj, g2, b2, out, nullptr);
}

// round 15
// speedup vs baseline: 1.0637x; 1.0637x over previous
#include <cuda_runtime.h>
#include <cuda_fp16.h>
#include <cstdint>

#define Bt  2
#define Ss  2048
#define Dd  1024
#define Hh  16
#define HDd 64
#define Tt  (Bt * Ss)      // 4096 tokens
#define DFF (4 * Dd)       // 4096
#define QKVS (3 * Dd)      // 3072

// ---------------- scratch (device globals; no allocation allowed) ----------------
__device__ float  g_proj[Tt * Dd];
__device__ float  g_x1[Tt * Dd];
__device__ float  g_bqkv[QKVS];
__device__ __half g_xh[Tt * Dd];
__device__ __half g_wqkvh[(size_t)Dd * QKVS];
__device__ __half g_woh[Dd * Dd];
__device__ __half g_wuph[(size_t)Dd * DFF];
__device__ __half g_wdnh[(size_t)DFF * Dd];
__device__ __half g_qkvh[(size_t)Tt * QKVS];
__device__ __half g_midh[Tt * Dd];
__device__ __half g_x1h[Tt * Dd];
__device__ __half g_uph[(size_t)Tt * DFF];

// ---------------- helpers ----------------
__device__ __forceinline__ void mma_f16(float* d, const uint32_t* a, const uint32_t* b) {
    asm volatile(
        "mma.sync.aligned.m16n8k16.row.col.f32.f16.f16.f32 "
        "{%0,%1,%2,%3}, {%4,%5,%6,%7}, {%8,%9}, {%0,%1,%2,%3};"
        : "+f"(d[0]), "+f"(d[1]), "+f"(d[2]), "+f"(d[3])
        : "r"(a[0]), "r"(a[1]), "r"(a[2]), "r"(a[3]), "r"(b[0]), "r"(b[1]));
}
__device__ __forceinline__ uint32_t sptr(const void* p) {
    return (uint32_t)__cvta_generic_to_shared(p);
}
__device__ __forceinline__ void ldsm_x4(uint32_t* r, uint32_t addr) {
    asm volatile("ldmatrix.sync.aligned.m8n8.x4.shared.b16 {%0,%1,%2,%3}, [%4];"
                 : "=r"(r[0]), "=r"(r[1]), "=r"(r[2]), "=r"(r[3]) : "r"(addr));
}
__device__ __forceinline__ void ldsm_x2t(uint32_t* r, uint32_t addr) {
    asm volatile("ldmatrix.sync.aligned.m8n8.x2.trans.shared.b16 {%0,%1}, [%2];"
                 : "=r"(r[0]), "=r"(r[1]) : "r"(addr));
}
__device__ __forceinline__ uint32_t packh2(float x, float y) {
    __half2 h = __floats2half2_rn(x, y);
    return *reinterpret_cast<uint32_t*>(&h);
}
__device__ __forceinline__ void cp_async16(uint32_t dst, const void* src) {
    asm volatile("cp.async.cg.shared.global [%0], [%1], 16;" :: "r"(dst), "l"(src));
}
__device__ __forceinline__ void cp_commit() {
    asm volatile("cp.async.commit_group;" ::: "memory");
}
template <int N>
__device__ __forceinline__ void cp_wait() {
    asm volatile("cp.async.wait_group %0;" :: "n"(N) : "memory");
}

// ---------------- fp32 -> fp16 converters (consolidated) ----------------
#define DD4 (Dd * Dd / 4)
__global__ __launch_bounds__(256)
void f2h_qkv(const float* __restrict__ Wq, const float* __restrict__ Wk,
             const float* __restrict__ Wv, __half* __restrict__ out)
{
    const int idx = blockIdx.x * 256 + threadIdx.x;
    const int seg = idx / DD4;
    const int j = (idx - seg * DD4) * 4;
    const float* W = (seg == 0) ? Wq : (seg == 1) ? Wk : Wv;
    const int r = j >> 10, c = j & 1023;
    float4 v = *(const float4*)&W[j];
    __half* o = out + (size_t)r * QKVS + seg * Dd + c;
    *(__half2*)&o[0] = __floats2half2_rn(v.x, v.y);
    *(__half2*)&o[2] = __floats2half2_rn(v.z, v.w);
}
__global__ __launch_bounds__(256)
void f2h_misc(const float* __restrict__ x,   const float* __restrict__ Wo,
              const float* __restrict__ Wup, const float* __restrict__ Wdn,
              __half* __restrict__ xh,   __half* __restrict__ woh,
              __half* __restrict__ wuph, __half* __restrict__ wdnh)
{
    const int c0 = Tt * Dd / 4, c1 = Dd * Dd / 4, c2 = Dd * DFF / 4;
    int idx = blockIdx.x * 256 + threadIdx.x;
    const float* in; __half* out;
    if (idx < c0)                 { in = x;   out = xh; }
    else if ((idx -= c0) < c1)    { in = Wo;  out = woh; }
    else if ((idx -= c1) < c2)    { in = Wup; out = wuph; }
    else { idx -= c2;               in = Wdn; out = wdnh; }
    const int j = idx * 4;
    float4 v = *(const float4*)&in[j];
    *(__half2*)&out[j]     = __floats2half2_rn(v.x, v.y);
    *(__half2*)&out[j + 2] = __floats2half2_rn(v.z, v.w);
}
__global__ __launch_bounds__(256)
void bias_concat_kernel(const float* __restrict__ bq, const float* __restrict__ bk,
                        const float* __restrict__ bv, float* __restrict__ out)
{
    const int i = blockIdx.x * 256 + threadIdx.x;
    if (i < Dd)            out[i] = bq[i];
    else if (i < 2 * Dd)   out[i] = bk[i - Dd];
    else if (i < 3 * Dd)   out[i] = bv[i - 2 * Dd];
}

// ---------------- FP16 GEMM (R11 best: 128x128, K-chunk 64, 2-stage, 64KB) ----------------
// A stage: 128 rows x 128B, phys16 = c ^ (r&7). B stage: 64 rows x 256B, same swizzle.
template <int RELU, int OUTH>
__global__ __launch_bounds__(256, 2)
void gemm_h(const __half* __restrict__ A, const __half* __restrict__ W,
            const float* __restrict__ bias, void* __restrict__ Cout,
            int M, int N, int K)
{
    extern __shared__ __align__(128) __half sm[];

    const int tid  = threadIdx.x;
    const int lane = tid & 31;
    const int wid  = tid >> 5;
    const int wm   = (wid & 1) * 64;
    const int wn   = (wid >> 1) * 32;
    const int m0   = blockIdx.y << 7;
    const int n0   = blockIdx.x << 7;

    const int row  = lane >> 2;
    const int col  = lane & 3;
    const int lrow = lane & 15;
    const int lc0  = lane >> 4;

    const uint32_t SA0 = sptr(sm);          // A: [0, 32768)
    const uint32_t SB0 = SA0 + 32768;       // B: [32768, 65536)

    const int a_r  = tid >> 3;
    const int a_cc = tid & 7;
    const int b_r  = tid >> 4;
    const int b_cc = tid & 15;

    const uint32_t dA = a_r * 128 + ((uint32_t)(a_cc ^ (a_r & 7)) << 4);
    const uint32_t dB = b_r * 256 + ((uint32_t)(b_cc ^ (b_r & 7)) << 4);

    float acc[4][4][4];
#pragma unroll
    for (int mi = 0; mi < 4; mi++)
#pragma unroll
        for (int ni = 0; ni < 4; ni++)
#pragma unroll
            for (int j = 0; j < 4; j++) acc[mi][ni][j] = 0.f;

    const int nk = K >> 6;

    auto load_stage = [&](int c, int st) {
        const __half* Ab = A + (size_t)(m0 + a_r) * K + (c << 6) + a_cc * 8;
        const uint32_t da = SA0 + st * 16384 + dA;
#pragma unroll
        for (int j = 0; j < 4; j++)
            cp_async16(da + j * 4096, Ab + (size_t)(32 * j) * K);
        const __half* Bb = W + (size_t)((c << 6) + b_r) * N + n0 + b_cc * 8;
        const uint32_t db = SB0 + st * 16384 + dB;
#pragma unroll
        for (int j = 0; j < 4; j++)
            cp_async16(db + j * 4096, Bb + (size_t)(16 * j) * N);
    };

    load_stage(0, 0);
    cp_commit();

    for (int c = 0; c < nk; c++) {
        const int st = c & 1;
        cp_wait<0>();
        __syncthreads();
        if (c + 1 < nk) { load_stage(c + 1, st ^ 1); cp_commit(); }

        const uint32_t SA = SA0 + st * 16384;
        const uint32_t SB = SB0 + st * 16384;

#pragma unroll
        for (int ks = 0; ks < 4; ks++) {
            uint32_t a[4][4], b[4][2];
#pragma unroll
            for (int mi = 0; mi < 4; mi++) {
                const int rr = wm + mi * 16 + lrow;
                ldsm_x4(a[mi], SA + rr * 128 +
                        ((uint32_t)((2 * ks + lc0) ^ (rr & 7)) << 4));
            }
#pragma unroll
            for (int ni = 0; ni < 4; ni++) {
                const int kr = ks * 16 + lrow;
                ldsm_x2t(b[ni], SB + kr * 256 +
                         ((uint32_t)((((wn >> 3) + ni)) ^ (kr & 7)) << 4));
            }
#pragma unroll
            for (int mi = 0; mi < 4; mi++)
#pragma unroll
                for (int ni = 0; ni < 4; ni++)
                    mma_f16(acc[mi][ni], a[mi], b[ni]);
        }
    }

#pragma unroll
    for (int mi = 0; mi < 4; mi++) {
        const int r0 = m0 + wm + mi * 16 + row;
#pragma unroll
        for (int ni = 0; ni < 4; ni++) {
            const int c0 = n0 + wn + ni * 8 + 2 * col;
            const float bb0 = bias[c0], bb1 = bias[c0 + 1];
            float v00 = acc[mi][ni][0] + bb0, v01 = acc[mi][ni][1] + bb1;
            float v10 = acc[mi][ni][2] + bb0, v11 = acc[mi][ni][3] + bb1;
            if (RELU) {
                v00 = fmaxf(v00, 0.f); v01 = fmaxf(v01, 0.f);
                v10 = fmaxf(v10, 0.f); v11 = fmaxf(v11, 0.f);
            }
            if (OUTH) {
                __half* Ch = (__half*)Cout;
                *(__half2*)&Ch[(size_t)r0 * N + c0]       = __floats2half2_rn(v00, v01);
                *(__half2*)&Ch[(size_t)(r0 + 8) * N + c0] = __floats2half2_rn(v10, v11);
            } else {
                float* Cf = (float*)Cout;
                *(float2*)&Cf[(size_t)r0 * N + c0]       = make_float2(v00, v01);
                *(float2*)&Cf[(size_t)(r0 + 8) * N + c0] = make_float2(v10, v11);
            }
        }
    }
}

// ---------------- FP16 causal flash attention (unchanged) ----------------
__global__ __launch_bounds__(256)
void attn_f16(const __half* __restrict__ QKV, __half* __restrict__ Og)
{
    __shared__ __half Ks[2][64][72];
    __shared__ __half Vs[2][64][72];

    const int tid  = threadIdx.x;
    const int lane = tid & 31;
    const int wid  = tid >> 5;
    const int g    = lane >> 2;
    const int t    = lane & 3;
    const int lrow = lane & 15;
    const int qb   = (int)gridDim.x - 1 - (int)blockIdx.x;
    const int bh   = blockIdx.y;
    const int b    = bh >> 4, h = bh & 15;

    const __half* Qb = QKV + (size_t)b * Ss * QKVS + h * HDd;
    const __half* Kb = Qb + Dd;
    const __half* Vb = Qb + 2 * Dd;

    const __half2 hs = __floats2half2_rn(0.125f, 0.125f);
    for (int i = tid; i < 128 * 8; i += 256) {
        const int r = i >> 3, c8 = (i & 7) * 8;
        uint4 q4 = *(const uint4*)&Qb[(size_t)(qb * 128 + r) * QKVS + c8];
        __half2* p = (__half2*)&q4;
        p[0] = __hmul2(p[0], hs); p[1] = __hmul2(p[1], hs);
        p[2] = __hmul2(p[2], hs); p[3] = __hmul2(p[3], hs);
        if (r < 64) *(uint4*)&Ks[0][r][c8]      = q4;
        else        *(uint4*)&Vs[0][r - 64][c8] = q4;
    }
    __syncthreads();

    uint32_t qf[4][4];
    {
        const __half (*Qs)[72] = (wid < 4) ? Ks[0] : Vs[0];
        const int qr = (wid * 16) % 64 + g;
#pragma unroll
        for (int s = 0; s < 4; s++) {
            qf[s][0] = *(const uint32_t*)&Qs[qr][s * 16 + 2 * t];
            qf[s][1] = *(const uint32_t*)&Qs[qr + 8][s * 16 + 2 * t];
            qf[s][2] = *(const uint32_t*)&Qs[qr][s * 16 + 2 * t + 8];
            qf[s][3] = *(const uint32_t*)&Qs[qr + 8][s * 16 + 2 * t + 8];
        }
    }
    __syncthreads();

    const int kv_r = tid >> 3;
    const int kv_c = (tid & 7) * 8;

    auto load_kv = [&](int kt, int st) {
#pragma unroll
        for (int j = 0; j < 2; j++) {
            const int r = kv_r + j * 32;
            const size_t off = (size_t)(kt * 64 + r) * QKVS + kv_c;
            cp_async16(sptr(&Ks[st][r][kv_c]), Kb + off);
            cp_async16(sptr(&Vs[st][r][kv_c]), Vb + off);
        }
    };

    load_kv(0, 0);
    cp_commit();

    float m0 = -1e30f, m1 = -1e30f, l0 = 0.f, l1 = 0.f;
    float O[8][4];
#pragma unroll
    for (int n = 0; n < 8; n++)
#pragma unroll
        for (int j = 0; j < 4; j++) O[n][j] = 0.f;

    const int lq0 = wid * 16 + g;
    const int qg0 = qb * 128 + lq0;
    const int qg1 = qg0 + 8;
    const int wmax = qb * 128 + wid * 16 + 15;

    const int nkt = 2 * qb + 2;
    for (int kt = 0; kt < nkt; kt++) {
        const int st = kt & 1;
        __syncthreads();
        if (kt + 1 < nkt) {
            load_kv(kt + 1, st ^ 1);
            cp_commit();
            cp_wait<1>();
        } else {
            cp_wait<0>();
        }
        __syncthreads();

        if (kt * 64 > wmax) continue;

        float S[8][4];
#pragma unroll
        for (int n = 0; n < 8; n++)
#pragma unroll
            for (int j = 0; j < 4; j++) S[n][j] = 0.f;

#pragma unroll
        for (int s = 0; s < 4; s++) {
#pragma unroll
            for (int n = 0; n < 8; n++) {
                uint32_t bq[2];
                bq[0] = *(const uint32_t*)&Ks[st][n * 8 + g][s * 16 + 2 * t];
                bq[1] = *(const uint32_t*)&Ks[st][n * 8 + g][s * 16 + 2 * t + 8];
                mma_f16(S[n], qf[s], bq);
            }
        }

        if (kt >= 2 * qb) {
#pragma unroll
            for (int n = 0; n < 8; n++) {
                const int kg = kt * 64 + n * 8 + 2 * t;
                if (kg     > qg0) S[n][0] = -1e30f;
                if (kg + 1 > qg0) S[n][1] = -1e30f;
                if (kg     > qg1) S[n][2] = -1e30f;
                if (kg + 1 > qg1) S[n][3] = -1e30f;
            }
        }

        float mx0 = -1e30f, mx1 = -1e30f;
#pragma unroll
        for (int n = 0; n < 8; n++) {
            mx0 = fmaxf(mx0, fmaxf(S[n][0], S[n][1]));
            mx1 = fmaxf(mx1, fmaxf(S[n][2], S[n][3]));
        }
        mx0 = fmaxf(mx0, __shfl_xor_sync(0xffffffffu, mx0, 1));
        mx0 = fmaxf(mx0, __shfl_xor_sync(0xffffffffu, mx0, 2));
        mx1 = fmaxf(mx1, __shfl_xor_sync(0xffffffffu, mx1, 1));
        mx1 = fmaxf(mx1, __shfl_xor_sync(0xffffffffu, mx1, 2));

        const float mn0 = fmaxf(m0, mx0), mn1 = fmaxf(m1, mx1);
        const float fac0 = __expf(m0 - mn0), fac1 = __expf(m1 - mn1);

        float s0 = 0.f, s1 = 0.f;
#pragma unroll
        for (int n = 0; n < 8; n++) {
            S[n][0] = __expf(S[n][0] - mn0);
            S[n][1] = __expf(S[n][1] - mn0);
            S[n][2] = __expf(S[n][2] - mn1);
            S[n][3] = __expf(S[n][3] - mn1);
            s0 += S[n][0] + S[n][1];
            s1 += S[n][2] + S[n][3];
        }
        s0 += __shfl_xor_sync(0xffffffffu, s0, 1);
        s0 += __shfl_xor_sync(0xffffffffu, s0, 2);
        s1 += __shfl_xor_sync(0xffffffffu, s1, 1);
        s1 += __shfl_xor_sync(0xffffffffu, s1, 2);

        l0 = l0 * fac0 + s0;
        l1 = l1 * fac1 + s1;
        m0 = mn0; m1 = mn1;

#pragma unroll
        for (int n = 0; n < 8; n++) {
            O[n][0] *= fac0; O[n][1] *= fac0;
            O[n][2] *= fac1; O[n][3] *= fac1;
        }

#pragma unroll
        for (int kk = 0; kk < 4; kk++) {
            uint32_t pa[4];
            pa[0] = packh2(S[2 * kk][0],     S[2 * kk][1]);
            pa[1] = packh2(S[2 * kk][2],     S[2 * kk][3]);
            pa[2] = packh2(S[2 * kk + 1][0], S[2 * kk + 1][1]);
            pa[3] = packh2(S[2 * kk + 1][2], S[2 * kk + 1][3]);
#pragma unroll
            for (int nd = 0; nd < 8; nd++) {
                uint32_t bv[2];
                ldsm_x2t(bv, sptr(&Vs[st][kk * 16 + lrow][nd * 8]));
                mma_f16(O[nd], pa, bv);
            }
        }
    }

    const float inv0 = 1.f / l0, inv1 = 1.f / l1;
    __half* o0 = Og + (size_t)(b * Ss + qb * 128 + lq0) * Dd + h * HDd;
    __half* o1 = o0 + 8 * Dd;
#pragma unroll
    for (int nd = 0; nd < 8; nd++) {
        const int c0 = nd * 8 + 2 * t;
        *(__half2*)&o0[c0] = __floats2half2_rn(O[nd][0] * inv0, O[nd][1] * inv0);
        *(__half2*)&o1[c0] = __floats2half2_rn(O[nd][2] * inv1, O[nd][3] * inv1);
    }
}

// ---------------- residual add + LayerNorm: register-resident float4 version ----------------
// 256 threads x 4 floats = one 1024-wide token row entirely in registers.
template <int DUAL>
__global__ __launch_bounds__(256)
void add_ln_kernel(const float* __restrict__ a, const float* __restrict__ r,
                   const float* __restrict__ gamma, const float* __restrict__ beta,
                   float* __restrict__ out, __half* __restrict__ outh)
{
    const int t = blockIdx.x;
    const int tid = threadIdx.x;
    const int i4 = tid * 4;
    __shared__ float red[18];

    const size_t base = (size_t)t * Dd + i4;
    float4 va = *(const float4*)&a[base];
    float4 vr = *(const float4*)&r[base];
    float v0 = va.x + vr.x, v1 = va.y + vr.y, v2 = va.z + vr.z, v3 = va.w + vr.w;

    float s  = (v0 + v1) + (v2 + v3);
    float sq = (v0 * v0 + v1 * v1) + (v2 * v2 + v3 * v3);
#pragma unroll
    for (int o = 16; o; o >>= 1) {
        s  += __shfl_xor_sync(0xffffffffu, s, o);
        sq += __shfl_xor_sync(0xffffffffu, sq, o);
    }
    if ((tid & 31) == 0) { red[tid >> 5] = s; red[8 + (tid >> 5)] = sq; }
    __syncthreads();
    if (tid < 32) {
        float ts = (tid < 8) ? red[tid] : 0.f;
        float tq = (tid < 8) ? red[8 + tid] : 0.f;
#pragma unroll
        for (int o = 4; o; o >>= 1) {
            ts += __shfl_xor_sync(0xffffffffu, ts, o);
            tq += __shfl_xor_sync(0xffffffffu, tq, o);
        }
        if (tid == 0) {
            const float mu  = ts * (1.0f / Dd);
            const float var = tq * (1.0f / Dd) - mu * mu;
            red[16] = mu;
            red[17] = rsqrtf(var + 1e-6f);
        }
    }
    __syncthreads();
    const float mu = red[16], rstd = red[17];

    const float4 gg = *(const float4*)&gamma[i4];
    const float4 bb = *(const float4*)&beta[i4];
    float4 o4;
    o4.x = (v0 - mu) * rstd * gg.x + bb.x;
    o4.y = (v1 - mu) * rstd * gg.y + bb.y;
    o4.z = (v2 - mu) * rstd * gg.z + bb.z;
    o4.w = (v3 - mu) * rstd * gg.w + bb.w;
    *(float4*)&out[base] = o4;
    if (DUAL) {
        uint2 h4;
        h4.x = packh2(o4.x, o4.y);
        h4.y = packh2(o4.z, o4.w);
        *(uint2*)&outh[base] = h4;
    }
}

// ---------------- launch ----------------
extern "C" void kernel_launch(void* const* d_in, const int* in_sizes, int n_in,
                              void* d_out, int out_size)
{
    const float* x   = (const float*)d_in[0];
    const float* Wq  = (const float*)d_in[1];
    const float* bq  = (const float*)d_in[2];
    const float* Wk  = (const float*)d_in[3];
    const float* bk  = (const float*)d_in[4];
    const float* Wv  = (const float*)d_in[5];
    const float* bv  = (const float*)d_in[6];
    const float* Wo  = (const float*)d_in[7];
    const float* bo  = (const float*)d_in[8];
    const float* g1  = (const float*)d_in[9];
    const float* b1  = (const float*)d_in[10];
    const float* Wup = (const float*)d_in[11];
    const float* bup = (const float*)d_in[12];
    const float* Wdn = (const float*)d_in[13];
    const float* bdn = (const float*)d_in[14];
    const float* g2  = (const float*)d_in[15];
    const float* b2  = (const float*)d_in[16];
    float* out = (float*)d_out;

    float *proj, *x1, *bqkv;
    __half *xh, *wqkvh, *woh, *wuph, *wdnh;
    __half *qkvh, *midh, *x1h, *uph;
    cudaGetSymbolAddress((void**)&proj,  g_proj);
    cudaGetSymbolAddress((void**)&x1,    g_x1);
    cudaGetSymbolAddress((void**)&bqkv,  g_bqkv);
    cudaGetSymbolAddress((void**)&xh,    g_xh);
    cudaGetSymbolAddress((void**)&wqkvh, g_wqkvh);
    cudaGetSymbolAddress((void**)&woh,   g_woh);
    cudaGetSymbolAddress((void**)&wuph,  g_wuph);
    cudaGetSymbolAddress((void**)&wdnh,  g_wdnh);
    cudaGetSymbolAddress((void**)&qkvh,  g_qkvh);
    cudaGetSymbolAddress((void**)&midh,  g_midh);
    cudaGetSymbolAddress((void**)&x1h,   g_x1h);
    cudaGetSymbolAddress((void**)&uph,   g_uph);

    const dim3 blk(256);
    const int SMEM = 65536;   // 64KB dynamic, 2 stages

    cudaFuncSetAttribute(gemm_h<0, 1>, cudaFuncAttributeMaxDynamicSharedMemorySize, SMEM);
    cudaFuncSetAttribute(gemm_h<0, 0>, cudaFuncAttributeMaxDynamicSharedMemorySize, SMEM);
    cudaFuncSetAttribute(gemm_h<1, 1>, cudaFuncAttributeMaxDynamicSharedMemorySize, SMEM);

    f2h_qkv<<<3 * (Dd * Dd / 4) / 256, blk>>>(Wq, Wk, Wv, wqkvh);
    {
        const int chunks = (Tt * Dd + Dd * Dd + Dd * DFF + DFF * Dd) / 4;
        f2h_misc<<<chunks / 256, blk>>>(x, Wo, Wup, Wdn, xh, woh, wuph, wdnh);
    }
    bias_concat_kernel<<<QKVS / 256, blk>>>(bq, bk, bv, bqkv);

    gemm_h<0, 1><<<dim3(QKVS / 128, Tt / 128), blk, SMEM>>>(xh, wqkvh, bqkv, qkvh, Tt, QKVS, Dd);

    attn_f16<<<dim3(Ss / 128, Bt * Hh), blk>>>(qkvh, midh);

    gemm_h<0, 0><<<dim3(Dd / 128, Tt / 128), blk, SMEM>>>(midh, woh, bo, proj, Tt, Dd, Dd);
    add_ln_kernel<1><<<Tt, blk>>>(x, proj, g1, b1, x1, x1h);

    gemm_h<1, 1><<<dim3(DFF / 128, Tt / 128), blk, SMEM>>>(x1h, wuph, bup, uph, Tt, DFF, Dd);
    gemm_h<0, 0><<<dim3(Dd / 128, Tt / 128), blk, SMEM>>>(uph, wdnh, bdn, proj, Tt, Dd, DFF);
    add_ln_kernel<0><<<Tt, blk>>>(x1, proj, g2, b2, out, nullptr);
}